// round 1
// baseline (speedup 1.0000x reference)
#include <cuda_runtime.h>
#include <cuda_bf16.h>

#define D 128
#define MAX_N 50000
#define TILE_ROWS 64
#define LDW 132   // padded row length for W tile (sW[k][o])
#define LDA 132   // padded row length for A tile (sA[r][k])
#define EDGES_PER_WARP 64

// Scratch for support = input @ W^T + b  (static device global: no allocs allowed)
__device__ float g_support[(size_t)MAX_N * D];

// ---------------------------------------------------------------------------
// Kernel 1: support[n][o] = sum_d input[n][d] * W[o][d] + b[o]
// Block: 256 threads, computes a 64x128 tile. Whole W (transposed) + 64-row
// input tile staged in shared. Each thread computes a 4(row) x 8(col) micro-tile.
// ---------------------------------------------------------------------------
__global__ __launch_bounds__(256) void gemm_support_kernel(
    const float* __restrict__ input,
    const float* __restrict__ W,
    const float* __restrict__ b,
    int N)
{
    extern __shared__ float smem[];
    float* sW = smem;                 // [128][LDW], sW[k*LDW + o] = W[o][k]
    float* sA = smem + 128 * LDW;     // [64][LDA],  sA[r*LDA + k]

    const int tid = threadIdx.x;
    const int rowBase = blockIdx.x * TILE_ROWS;

    // Load W transposed into shared: sW[k][o] = W[o*128 + k]
    #pragma unroll
    for (int idx = tid; idx < D * D; idx += 256) {
        int o = idx >> 7;
        int k = idx & 127;
        sW[k * LDW + o] = W[idx];
    }

    // Load 64 input rows (float4, coalesced), zero-pad past N
    #pragma unroll
    for (int i = 0; i < (TILE_ROWS * D / 4) / 256; ++i) {
        int idx4 = tid + i * 256;          // float4 index within tile
        int r  = idx4 >> 5;                // 32 float4 per row
        int kk = (idx4 & 31) << 2;
        float4 v = make_float4(0.f, 0.f, 0.f, 0.f);
        int row = rowBase + r;
        if (row < N)
            v = *reinterpret_cast<const float4*>(&input[(size_t)row * D + kk]);
        *reinterpret_cast<float4*>(&sA[r * LDA + kk]) = v;
    }
    __syncthreads();

    const int cg = tid & 15;   // col group: 8 consecutive output cols
    const int rg = tid >> 4;   // row group: 4 consecutive rows

    float acc[4][8];
    #pragma unroll
    for (int i = 0; i < 4; ++i)
        #pragma unroll
        for (int j = 0; j < 8; ++j)
            acc[i][j] = 0.f;

    for (int k0 = 0; k0 < D; k0 += 4) {
        float4 a[4];
        #pragma unroll
        for (int i = 0; i < 4; ++i)
            a[i] = *reinterpret_cast<const float4*>(&sA[(rg * 4 + i) * LDA + k0]);

        #pragma unroll
        for (int kk = 0; kk < 4; ++kk) {
            const float4 w0 = *reinterpret_cast<const float4*>(&sW[(k0 + kk) * LDW + cg * 8]);
            const float4 w1 = *reinterpret_cast<const float4*>(&sW[(k0 + kk) * LDW + cg * 8 + 4]);
            #pragma unroll
            for (int i = 0; i < 4; ++i) {
                const float av = (kk == 0) ? a[i].x : (kk == 1) ? a[i].y
                               : (kk == 2) ? a[i].z : a[i].w;
                acc[i][0] += av * w0.x;
                acc[i][1] += av * w0.y;
                acc[i][2] += av * w0.z;
                acc[i][3] += av * w0.w;
                acc[i][4] += av * w1.x;
                acc[i][5] += av * w1.y;
                acc[i][6] += av * w1.z;
                acc[i][7] += av * w1.w;
            }
        }
    }

    const float4 b0 = *reinterpret_cast<const float4*>(&b[cg * 8]);
    const float4 b1 = *reinterpret_cast<const float4*>(&b[cg * 8 + 4]);

    #pragma unroll
    for (int i = 0; i < 4; ++i) {
        int row = rowBase + rg * 4 + i;
        if (row < N) {
            float4 o0 = make_float4(acc[i][0] + b0.x, acc[i][1] + b0.y,
                                    acc[i][2] + b0.z, acc[i][3] + b0.w);
            float4 o1 = make_float4(acc[i][4] + b1.x, acc[i][5] + b1.y,
                                    acc[i][6] + b1.z, acc[i][7] + b1.w);
            *reinterpret_cast<float4*>(&g_support[(size_t)row * D + cg * 8])     = o0;
            *reinterpret_cast<float4*>(&g_support[(size_t)row * D + cg * 8 + 4]) = o1;
        }
    }
}

// ---------------------------------------------------------------------------
// Kernel 2: COO scatter, exploiting sorted adj_row.
// One warp per EDGES_PER_WARP-edge chunk. Each lane owns 4 columns (float4).
// Register-accumulate runs of equal rows; rows fully inside a chunk get a
// plain store (exclusive ownership thanks to sorting), boundary rows (first
// row of chunk + final pending row) use atomicAdd.
// ---------------------------------------------------------------------------
__device__ __forceinline__ void flush_row(float* __restrict__ out, int curRow,
                                          int lane, const float4& acc,
                                          int firstRow, bool isFinal)
{
    if (curRow < 0) return;
    float* p = out + (size_t)curRow * D + lane * 4;
    if (curRow == firstRow || isFinal) {
        atomicAdd(p + 0, acc.x);
        atomicAdd(p + 1, acc.y);
        atomicAdd(p + 2, acc.z);
        atomicAdd(p + 3, acc.w);
    } else {
        *reinterpret_cast<float4*>(p) = acc;
    }
}

__global__ __launch_bounds__(256) void scatter_kernel(
    const int* __restrict__ adj_row,
    const int* __restrict__ adj_col,
    const float* __restrict__ adj_val,
    float* __restrict__ out,
    int E)
{
    const int warpId = (blockIdx.x * blockDim.x + threadIdx.x) >> 5;
    const int lane = threadIdx.x & 31;
    const int base = warpId * EDGES_PER_WARP;
    if (base >= E) return;

    const int firstRow = adj_row[base];
    int curRow = -1;
    float4 acc = make_float4(0.f, 0.f, 0.f, 0.f);

    for (int t = 0; t < EDGES_PER_WARP; t += 32) {
        const int e = base + t + lane;
        int r = -2, c = 0;
        float v = 0.f;
        if (e < E) { r = adj_row[e]; c = adj_col[e]; v = adj_val[e]; }

        #pragma unroll
        for (int j = 0; j < 32; ++j) {
            const int   rj = __shfl_sync(0xFFFFFFFFu, r, j);
            const int   cj = __shfl_sync(0xFFFFFFFFu, c, j);
            const float vj = __shfl_sync(0xFFFFFFFFu, v, j);
            if (rj < 0) break;   // trailing invalid edges (uniform)
            if (rj != curRow) {
                flush_row(out, curRow, lane, acc, firstRow, false);
                curRow = rj;
                acc = make_float4(0.f, 0.f, 0.f, 0.f);
            }
            const float4 s = *reinterpret_cast<const float4*>(
                &g_support[(size_t)cj * D + lane * 4]);
            acc.x += vj * s.x;
            acc.y += vj * s.y;
            acc.z += vj * s.z;
            acc.w += vj * s.w;
        }
    }
    flush_row(out, curRow, lane, acc, firstRow, true);
}

// ---------------------------------------------------------------------------
// Kernel 3: elementwise tanh
// ---------------------------------------------------------------------------
__global__ __launch_bounds__(256) void tanh_kernel(float* __restrict__ out, int n4)
{
    const int i = blockIdx.x * blockDim.x + threadIdx.x;
    if (i < n4) {
        float4 v = reinterpret_cast<float4*>(out)[i];
        v.x = tanhf(v.x);
        v.y = tanhf(v.y);
        v.z = tanhf(v.z);
        v.w = tanhf(v.w);
        reinterpret_cast<float4*>(out)[i] = v;
    }
}

// ---------------------------------------------------------------------------
extern "C" void kernel_launch(void* const* d_in, const int* in_sizes, int n_in,
                              void* d_out, int out_size)
{
    const float* input   = (const float*)d_in[0];
    const float* W       = (const float*)d_in[1];
    const float* b       = (const float*)d_in[2];
    const int*   adj_row = (const int*)d_in[3];
    const int*   adj_col = (const int*)d_in[4];
    const float* adj_val = (const float*)d_in[5];
    float* out = (float*)d_out;

    const int N = in_sizes[0] / D;
    const int E = in_sizes[3];

    // Zero the output (it is poisoned); scatter accumulates into it.
    cudaMemsetAsync(d_out, 0, (size_t)N * D * sizeof(float));

    // GEMM: support = input @ W^T + b
    const int smemBytes = (128 * LDW + TILE_ROWS * LDA) * sizeof(float);
    cudaFuncSetAttribute(gemm_support_kernel,
                         cudaFuncAttributeMaxDynamicSharedMemorySize, smemBytes);
    const int gemmBlocks = (N + TILE_ROWS - 1) / TILE_ROWS;
    gemm_support_kernel<<<gemmBlocks, 256, smemBytes>>>(input, W, b, N);

    // Scatter (sorted COO) into out
    const int nWarps = (E + EDGES_PER_WARP - 1) / EDGES_PER_WARP;
    const int scatterBlocks = (nWarps * 32 + 255) / 256;
    scatter_kernel<<<scatterBlocks, 256>>>(adj_row, adj_col, adj_val, out, E);

    // tanh in place
    const int n4 = N * D / 4;
    tanh_kernel<<<(n4 + 255) / 256, 256>>>(out, n4);
}